// round 9
// baseline (speedup 1.0000x reference)
#include <cuda_runtime.h>

#define BATCH       32768
#define NUM_CLASSES 1000
#define FEAT_DIM    128

#define S1_BLOCKS   1024
#define S1_THREADS  256
#define WARPS_PER_BLOCK (S1_THREADS / 32)            // 8
#define TOTAL_WARPS (S1_BLOCKS * WARPS_PER_BLOCK)    // 8192
#define ROWS_PER_WARP (BATCH / TOTAL_WARPS)          // 4

__device__ float        g_partial[S1_BLOCKS];
__device__ unsigned int g_count = 0;

__global__ void __launch_bounds__(S1_THREADS, 4)     // allow up to 64 regs/thread
center_loss_fused(const float* __restrict__ y,
                  const int* __restrict__ labels,
                  const float* __restrict__ centers,
                  const float* __restrict__ loss_weight,
                  float* __restrict__ out)
{
    const int lane   = threadIdx.x & 31;
    const int warpId = threadIdx.x >> 5;
    const int gwarp  = blockIdx.x * WARPS_PER_BLOCK + warpId;

    const float4* __restrict__ y4 = (const float4*)y;
    const float4* __restrict__ c4 = (const float4*)centers;

    // ---- front-batched loads: all independent requests in flight ----
    int cls[ROWS_PER_WARP];
    #pragma unroll
    for (int k = 0; k < ROWS_PER_WARP; k++)
        cls[k] = __ldg(&labels[gwarp + k * TOTAL_WARPS]);    // 4 independent

    float4 yv[ROWS_PER_WARP];
    #pragma unroll
    for (int k = 0; k < ROWS_PER_WARP; k++) {
        const int row = gwarp + k * TOTAL_WARPS;
        yv[k] = y4[row * (FEAT_DIM / 4) + lane];             // 4 independent
    }

    float4 cv[ROWS_PER_WARP];
    #pragma unroll
    for (int k = 0; k < ROWS_PER_WARP; k++)
        cv[k] = __ldg(&c4[cls[k] * (FEAT_DIM / 4) + lane]);  // waits only on own label

    // ---- math: (y-c)^2, two accumulator chains ----
    float acc0 = 0.0f, acc1 = 0.0f;
    #pragma unroll
    for (int k = 0; k < ROWS_PER_WARP; k++) {
        float dx = yv[k].x - cv[k].x;
        float dy = yv[k].y - cv[k].y;
        float dz = yv[k].z - cv[k].z;
        float dw = yv[k].w - cv[k].w;
        float s = dx * dx + dy * dy + dz * dz + dw * dw;
        if (k & 1) acc1 += s; else acc0 += s;
    }
    float acc = acc0 + acc1;

    // ---- warp reduce ----
    #pragma unroll
    for (int off = 16; off > 0; off >>= 1)
        acc += __shfl_xor_sync(0xFFFFFFFFu, acc, off);

    // ---- block reduce ----
    __shared__ float smem[WARPS_PER_BLOCK];
    if (lane == 0) smem[warpId] = acc;
    __syncthreads();

    __shared__ bool isLast;
    if (threadIdx.x == 0) {
        float t = 0.0f;
        #pragma unroll
        for (int i = 0; i < WARPS_PER_BLOCK; i++) t += smem[i];
        g_partial[blockIdx.x] = t;
        __threadfence();
        unsigned int prev = atomicAdd(&g_count, 1u);
        isLast = (prev == (unsigned int)(gridDim.x - 1));
    }
    __syncthreads();

    // ---- last block: deterministic final reduce over 1024 partials ----
    if (isLast) {
        __shared__ float fin[S1_THREADS];
        float t = 0.0f;
        #pragma unroll
        for (int i = 0; i < S1_BLOCKS / S1_THREADS; i++)
            t += g_partial[threadIdx.x + i * S1_THREADS];
        fin[threadIdx.x] = t;
        __syncthreads();

        for (int off = S1_THREADS / 2; off > 0; off >>= 1) {
            if (threadIdx.x < off) fin[threadIdx.x] += fin[threadIdx.x + off];
            __syncthreads();
        }

        if (threadIdx.x == 0) {
            // masked-matrix zeros clip to 1e-12: + B*(C-1)*1e-12, then /B
            float clip_term = (float)((double)BATCH * (double)(NUM_CLASSES - 1) * 1e-12);
            float total = fin[0] + clip_term;
            out[0] = (total / (float)BATCH) * loss_weight[0];
            g_count = 0;  // reset for next graph replay
        }
    }
}

extern "C" void kernel_launch(void* const* d_in, const int* in_sizes, int n_in,
                              void* d_out, int out_size)
{
    // Identify inputs by element count (all distinct):
    //   y: 4194304, centers: 128000, labels: 32768, loss_weight: 1
    const float* y       = nullptr;
    const int*   labels  = nullptr;
    const float* centers = nullptr;
    const float* lw      = nullptr;

    for (int i = 0; i < n_in; i++) {
        switch (in_sizes[i]) {
            case BATCH * FEAT_DIM:       y       = (const float*)d_in[i]; break;
            case NUM_CLASSES * FEAT_DIM: centers = (const float*)d_in[i]; break;
            case BATCH:                  labels  = (const int*)d_in[i];   break;
            case 1:                      lw      = (const float*)d_in[i]; break;
            default: break;
        }
    }

    center_loss_fused<<<S1_BLOCKS, S1_THREADS>>>(y, labels, centers, lw, (float*)d_out);
}

// round 10
// speedup vs baseline: 1.1505x; 1.1505x over previous
#include <cuda_runtime.h>

#define BATCH       32768
#define NUM_CLASSES 1000
#define FEAT_DIM    128

#define S1_BLOCKS   512
#define S1_THREADS  256
#define WARPS_PER_BLOCK (S1_THREADS / 32)            // 8
#define TOTAL_WARPS (S1_BLOCKS * WARPS_PER_BLOCK)    // 4096
#define ROWS_PER_WARP (BATCH / TOTAL_WARPS)          // 8

__device__ float        g_partial[S1_BLOCKS];
__device__ unsigned int g_count = 0;

__global__ void __launch_bounds__(S1_THREADS)
center_loss_fused(const float* __restrict__ y,
                  const int* __restrict__ labels,
                  const float* __restrict__ centers,
                  const float* __restrict__ loss_weight,
                  float* __restrict__ out)
{
    const int lane   = threadIdx.x & 31;
    const int warpId = threadIdx.x >> 5;
    const int gwarp  = blockIdx.x * WARPS_PER_BLOCK + warpId;

    const float4* __restrict__ y4 = (const float4*)y;
    const float4* __restrict__ c4 = (const float4*)centers;

    // rolled load-use loop: the schedule that wins on this chip
    // (front-batching loses to cross-CTA L1tex queue contention)
    float acc0 = 0.0f, acc1 = 0.0f;

    #pragma unroll
    for (int k = 0; k < ROWS_PER_WARP; k++) {
        const int row = gwarp + k * TOTAL_WARPS;
        const int cls = __ldg(&labels[row]);                 // warp-uniform broadcast
        float4 yv = y4[row * (FEAT_DIM / 4) + lane];
        float4 cv = __ldg(&c4[cls * (FEAT_DIM / 4) + lane]);

        float dx = yv.x - cv.x;
        float dy = yv.y - cv.y;
        float dz = yv.z - cv.z;
        float dw = yv.w - cv.w;
        float s = dx * dx + dy * dy + dz * dz + dw * dw;
        if (k & 1) acc1 += s; else acc0 += s;
    }
    float acc = acc0 + acc1;

    // ---- warp reduce ----
    #pragma unroll
    for (int off = 16; off > 0; off >>= 1)
        acc += __shfl_xor_sync(0xFFFFFFFFu, acc, off);

    // ---- block reduce ----
    __shared__ float smem[WARPS_PER_BLOCK];
    if (lane == 0) smem[warpId] = acc;
    __syncthreads();

    __shared__ bool isLast;
    if (threadIdx.x == 0) {
        float t = 0.0f;
        #pragma unroll
        for (int i = 0; i < WARPS_PER_BLOCK; i++) t += smem[i];
        g_partial[blockIdx.x] = t;
        __threadfence();
        unsigned int prev = atomicAdd(&g_count, 1u);
        isLast = (prev == (unsigned int)(gridDim.x - 1));
    }
    __syncthreads();

    // ---- last block: deterministic final reduce over 512 partials ----
    if (isLast) {
        __shared__ float fin[S1_THREADS];
        float t = 0.0f;
        #pragma unroll
        for (int i = 0; i < S1_BLOCKS / S1_THREADS; i++)
            t += g_partial[threadIdx.x + i * S1_THREADS];
        fin[threadIdx.x] = t;
        __syncthreads();

        for (int off = S1_THREADS / 2; off > 0; off >>= 1) {
            if (threadIdx.x < off) fin[threadIdx.x] += fin[threadIdx.x + off];
            __syncthreads();
        }

        if (threadIdx.x == 0) {
            // masked-matrix zeros clip to 1e-12: + B*(C-1)*1e-12, then /B
            float clip_term = (float)((double)BATCH * (double)(NUM_CLASSES - 1) * 1e-12);
            float total = fin[0] + clip_term;
            out[0] = (total / (float)BATCH) * loss_weight[0];
            g_count = 0;  // reset for next graph replay
        }
    }
}

extern "C" void kernel_launch(void* const* d_in, const int* in_sizes, int n_in,
                              void* d_out, int out_size)
{
    // Identify inputs by element count (all distinct):
    //   y: 4194304, centers: 128000, labels: 32768, loss_weight: 1
    const float* y       = nullptr;
    const int*   labels  = nullptr;
    const float* centers = nullptr;
    const float* lw      = nullptr;

    for (int i = 0; i < n_in; i++) {
        switch (in_sizes[i]) {
            case BATCH * FEAT_DIM:       y       = (const float*)d_in[i]; break;
            case NUM_CLASSES * FEAT_DIM: centers = (const float*)d_in[i]; break;
            case BATCH:                  labels  = (const int*)d_in[i];   break;
            case 1:                      lw      = (const float*)d_in[i]; break;
            default: break;
        }
    }

    center_loss_fused<<<S1_BLOCKS, S1_THREADS>>>(y, labels, centers, lw, (float*)d_out);
}

// round 11
// speedup vs baseline: 1.1801x; 1.0257x over previous
#include <cuda_runtime.h>

#define BATCH       32768
#define NUM_CLASSES 1000
#define FEAT_DIM    128

#define S1_BLOCKS   1024
#define S1_THREADS  256
#define WARPS_PER_BLOCK (S1_THREADS / 32)            // 8
#define TOTAL_WARPS (S1_BLOCKS * WARPS_PER_BLOCK)    // 8192
#define ROWS_PER_WARP (BATCH / TOTAL_WARPS)          // 4

__device__ float        g_partial[S1_BLOCKS];
__device__ unsigned int g_count = 0;

__global__ void __launch_bounds__(S1_THREADS)
center_loss_fused(const float* __restrict__ y,
                  const int* __restrict__ labels,
                  const float* __restrict__ centers,
                  const float* __restrict__ loss_weight,
                  float* __restrict__ out)
{
    const int lane   = threadIdx.x & 31;
    const int warpId = threadIdx.x >> 5;
    const int gwarp  = blockIdx.x * WARPS_PER_BLOCK + warpId;

    const float4* __restrict__ y4 = (const float4*)y;
    const float4* __restrict__ c4 = (const float4*)centers;

    // ---- preload labels: 4 independent scalar loads (R8 winner schedule) ----
    int cls[ROWS_PER_WARP];
    #pragma unroll
    for (int k = 0; k < ROWS_PER_WARP; k++)
        cls[k] = __ldg(&labels[gwarp + k * TOTAL_WARPS]);

    // ---- rolled load-use mainloop: empirically optimal on this chip ----
    float acc0 = 0.0f, acc1 = 0.0f;

    #pragma unroll
    for (int k = 0; k < ROWS_PER_WARP; k++) {
        const int row = gwarp + k * TOTAL_WARPS;
        float4 yv = y4[row * (FEAT_DIM / 4) + lane];
        float4 cv = __ldg(&c4[cls[k] * (FEAT_DIM / 4) + lane]);

        float dx = yv.x - cv.x;
        float dy = yv.y - cv.y;
        float dz = yv.z - cv.z;
        float dw = yv.w - cv.w;
        float s = dx * dx + dy * dy + dz * dz + dw * dw;
        if (k & 1) acc1 += s; else acc0 += s;
    }
    float acc = acc0 + acc1;

    // ---- warp reduce ----
    #pragma unroll
    for (int off = 16; off > 0; off >>= 1)
        acc += __shfl_xor_sync(0xFFFFFFFFu, acc, off);

    // ---- block reduce ----
    __shared__ float smem[WARPS_PER_BLOCK];
    if (lane == 0) smem[warpId] = acc;
    __syncthreads();

    __shared__ bool isLast;
    if (threadIdx.x == 0) {
        float t = 0.0f;
        #pragma unroll
        for (int i = 0; i < WARPS_PER_BLOCK; i++) t += smem[i];
        g_partial[blockIdx.x] = t;
        __threadfence();
        unsigned int prev = atomicAdd(&g_count, 1u);
        isLast = (prev == (unsigned int)(gridDim.x - 1));
    }
    __syncthreads();

    // ---- last block: shuffle-based final reduce (2 barriers, not 8) ----
    if (isLast) {
        float t = 0.0f;
        #pragma unroll
        for (int i = 0; i < S1_BLOCKS / S1_THREADS; i++)
            t += g_partial[threadIdx.x + i * S1_THREADS];

        #pragma unroll
        for (int off = 16; off > 0; off >>= 1)
            t += __shfl_xor_sync(0xFFFFFFFFu, t, off);

        __shared__ float wsum[WARPS_PER_BLOCK];
        if (lane == 0) wsum[warpId] = t;
        __syncthreads();

        if (warpId == 0) {
            float v = (lane < WARPS_PER_BLOCK) ? wsum[lane] : 0.0f;
            #pragma unroll
            for (int off = 4; off > 0; off >>= 1)
                v += __shfl_xor_sync(0xFFFFFFFFu, v, off);

            if (lane == 0) {
                // masked-matrix zeros clip to 1e-12: + B*(C-1)*1e-12, then /B
                float clip_term = (float)((double)BATCH * (double)(NUM_CLASSES - 1) * 1e-12);
                float total = v + clip_term;
                out[0] = (total / (float)BATCH) * loss_weight[0];
                g_count = 0;  // reset for next graph replay
            }
        }
    }
}

extern "C" void kernel_launch(void* const* d_in, const int* in_sizes, int n_in,
                              void* d_out, int out_size)
{
    // Identify inputs by element count (all distinct):
    //   y: 4194304, centers: 128000, labels: 32768, loss_weight: 1
    const float* y       = nullptr;
    const int*   labels  = nullptr;
    const float* centers = nullptr;
    const float* lw      = nullptr;

    for (int i = 0; i < n_in; i++) {
        switch (in_sizes[i]) {
            case BATCH * FEAT_DIM:       y       = (const float*)d_in[i]; break;
            case NUM_CLASSES * FEAT_DIM: centers = (const float*)d_in[i]; break;
            case BATCH:                  labels  = (const int*)d_in[i];   break;
            case 1:                      lw      = (const float*)d_in[i]; break;
            default: break;
        }
    }

    center_loss_fused<<<S1_BLOCKS, S1_THREADS>>>(y, labels, centers, lw, (float*)d_out);
}

// round 12
// speedup vs baseline: 1.1845x; 1.0037x over previous
#include <cuda_runtime.h>

#define BATCH       32768
#define NUM_CLASSES 1000
#define FEAT_DIM    128

#define S1_BLOCKS   1024
#define S1_THREADS  256
#define WARPS_PER_BLOCK (S1_THREADS / 32)            // 8
#define TOTAL_WARPS (S1_BLOCKS * WARPS_PER_BLOCK)    // 8192
#define ROWS_PER_WARP (BATCH / TOTAL_WARPS)          // 4

__device__ float        g_partial[S1_BLOCKS];
__device__ unsigned int g_count = 0;

__global__ void __launch_bounds__(S1_THREADS)
center_loss_fused(const float* __restrict__ y,
                  const int* __restrict__ labels,
                  const float* __restrict__ centers,
                  const float* __restrict__ loss_weight,
                  float* __restrict__ out)
{
    const int lane   = threadIdx.x & 31;
    const int warpId = threadIdx.x >> 5;
    const int gwarp  = blockIdx.x * WARPS_PER_BLOCK + warpId;

    const float4* __restrict__ y4 = (const float4*)y;
    const float4* __restrict__ c4 = (const float4*)centers;

    // ---- contiguous rows per warp: labels are one aligned int4 load ----
    const int row0 = gwarp * ROWS_PER_WARP;
    const int4 lab4 = __ldg((const int4*)&labels[row0]);
    int cls[ROWS_PER_WARP] = { lab4.x, lab4.y, lab4.z, lab4.w };

    // ---- rolled load-use mainloop (R8 winner schedule); y reads are one
    //      contiguous 2KB block per warp ----
    float acc0 = 0.0f, acc1 = 0.0f;

    #pragma unroll
    for (int k = 0; k < ROWS_PER_WARP; k++) {
        const int row = row0 + k;
        float4 yv = y4[row * (FEAT_DIM / 4) + lane];
        float4 cv = __ldg(&c4[cls[k] * (FEAT_DIM / 4) + lane]);

        float dx = yv.x - cv.x;
        float dy = yv.y - cv.y;
        float dz = yv.z - cv.z;
        float dw = yv.w - cv.w;
        float s = dx * dx + dy * dy + dz * dz + dw * dw;
        if (k & 1) acc1 += s; else acc0 += s;
    }
    float acc = acc0 + acc1;

    // ---- warp reduce ----
    #pragma unroll
    for (int off = 16; off > 0; off >>= 1)
        acc += __shfl_xor_sync(0xFFFFFFFFu, acc, off);

    // ---- block reduce ----
    __shared__ float smem[WARPS_PER_BLOCK];
    if (lane == 0) smem[warpId] = acc;
    __syncthreads();

    __shared__ bool isLast;
    if (threadIdx.x == 0) {
        float t = 0.0f;
        #pragma unroll
        for (int i = 0; i < WARPS_PER_BLOCK; i++) t += smem[i];
        g_partial[blockIdx.x] = t;
        __threadfence();
        unsigned int prev = atomicAdd(&g_count, 1u);
        isLast = (prev == (unsigned int)(gridDim.x - 1));
    }
    __syncthreads();

    // ---- last block: shuffle-based final reduce (2 barriers) ----
    if (isLast) {
        float t = 0.0f;
        #pragma unroll
        for (int i = 0; i < S1_BLOCKS / S1_THREADS; i++)
            t += g_partial[threadIdx.x + i * S1_THREADS];

        #pragma unroll
        for (int off = 16; off > 0; off >>= 1)
            t += __shfl_xor_sync(0xFFFFFFFFu, t, off);

        __shared__ float wsum[WARPS_PER_BLOCK];
        if (lane == 0) wsum[warpId] = t;
        __syncthreads();

        if (warpId == 0) {
            float v = (lane < WARPS_PER_BLOCK) ? wsum[lane] : 0.0f;
            #pragma unroll
            for (int off = 4; off > 0; off >>= 1)
                v += __shfl_xor_sync(0xFFFFFFFFu, v, off);

            if (lane == 0) {
                // masked-matrix zeros clip to 1e-12: + B*(C-1)*1e-12, then /B
                float clip_term = (float)((double)BATCH * (double)(NUM_CLASSES - 1) * 1e-12);
                float total = v + clip_term;
                out[0] = (total / (float)BATCH) * loss_weight[0];
                g_count = 0;  // reset for next graph replay
            }
        }
    }
}

extern "C" void kernel_launch(void* const* d_in, const int* in_sizes, int n_in,
                              void* d_out, int out_size)
{
    // Identify inputs by element count (all distinct):
    //   y: 4194304, centers: 128000, labels: 32768, loss_weight: 1
    const float* y       = nullptr;
    const int*   labels  = nullptr;
    const float* centers = nullptr;
    const float* lw      = nullptr;

    for (int i = 0; i < n_in; i++) {
        switch (in_sizes[i]) {
            case BATCH * FEAT_DIM:       y       = (const float*)d_in[i]; break;
            case NUM_CLASSES * FEAT_DIM: centers = (const float*)d_in[i]; break;
            case BATCH:                  labels  = (const int*)d_in[i];   break;
            case 1:                      lw      = (const float*)d_in[i]; break;
            default: break;
        }
    }

    center_loss_fused<<<S1_BLOCKS, S1_THREADS>>>(y, labels, centers, lw, (float*)d_out);
}